// round 1
// baseline (speedup 1.0000x reference)
#include <cuda_runtime.h>
#include <cuda_bf16.h>
#include <math.h>

// Problem dims
#define BB 32
#define TT 256
#define EE 512
#define HH 512
#define GG 2048   // 4*H
#define CC 9
#define MTOT (BB*TT)          // 8192
#define LSTM_BLOCKS 128       // 64 per direction
#define LSTM_SMEM_FLOATS (32*516 + 512*32 + 32*33)
#define LSTM_SMEM_BYTES (LSTM_SMEM_FLOATS*4)

// ---------------- device scratch (static, no runtime allocation) -------------
__device__ float g_x[MTOT*EE];                 // gathered embeddings [m][512]
__device__ float g_xp[2L*TT*BB*GG];            // [dir][t][b][2048]
__device__ float g_hcat[(size_t)MTOT*1024];    // [b*256+t][hf(512)|hb(512)]
__device__ float g_hst[3*2*HH*BB];             // [par][dir][k][b]
__device__ float g_emis[MTOT*CC];              // [b*256+t][9]
__device__ float g_llh[BB];
__device__ int   g_flags[LSTM_BLOCKS];
__device__ unsigned g_barcnt;                  // zero-initialized at load
__device__ unsigned g_bargen;

// ---------------- kernel 1: embedding gather (zero row 0) --------------------
__global__ void k_gather(const int* __restrict__ inp, const float* __restrict__ emb) {
    int m = blockIdx.x;
    int tok = inp[m];
    float4* dst = (float4*)(g_x + (size_t)m * EE);
    if (tok == 0) {
        float4 z = make_float4(0.f, 0.f, 0.f, 0.f);
        for (int i = threadIdx.x; i < EE/4; i += blockDim.x) dst[i] = z;
    } else {
        const float4* src = (const float4*)(emb + (size_t)tok * EE);
        for (int i = threadIdx.x; i < EE/4; i += blockDim.x) dst[i] = src[i];
    }
}

// ---------------- kernel 2: xp = x @ W_ih^T + b_ih + b_hh  (both dirs) -------
// 128x128 tile, BK=8, 256 threads, 8x8 per thread (split 4+4 rows/cols)
__global__ __launch_bounds__(256, 2) void k_xpgemm(
    const float* __restrict__ wf, const float* __restrict__ wb,
    const float* __restrict__ bihf, const float* __restrict__ bhhf,
    const float* __restrict__ bihb, const float* __restrict__ bhhb)
{
    __shared__ float As[8][132];
    __shared__ float Bs[8][132];

    int ntile = blockIdx.x;            // 0..31 over 4096 cols
    int m0 = blockIdx.y * 128;
    int dir = (ntile >= 16) ? 1 : 0;
    int nloc0 = (ntile & 15) * 128;
    const float* w   = dir ? wb : wf;
    const float* bih = dir ? bihb : bihf;
    const float* bhh = dir ? bhhb : bhhf;

    int tid = threadIdx.x;
    int tx = tid & 15, ty = tid >> 4;
    int lrow = tid >> 1;
    int lk4  = (tid & 1) * 4;

    float acc[8][8];
#pragma unroll
    for (int i = 0; i < 8; i++)
#pragma unroll
        for (int j = 0; j < 8; j++) acc[i][j] = 0.f;

    for (int kt = 0; kt < EE; kt += 8) {
        float4 av = *(const float4*)(g_x + (size_t)(m0 + lrow) * EE + kt + lk4);
        float4 bv = *(const float4*)(w   + (size_t)(nloc0 + lrow) * EE + kt + lk4);
        As[lk4+0][lrow] = av.x; As[lk4+1][lrow] = av.y;
        As[lk4+2][lrow] = av.z; As[lk4+3][lrow] = av.w;
        Bs[lk4+0][lrow] = bv.x; Bs[lk4+1][lrow] = bv.y;
        Bs[lk4+2][lrow] = bv.z; Bs[lk4+3][lrow] = bv.w;
        __syncthreads();
#pragma unroll
        for (int k = 0; k < 8; k++) {
            float4 a0 = *(const float4*)&As[k][ty*4];
            float4 a1 = *(const float4*)&As[k][64 + ty*4];
            float4 b0 = *(const float4*)&Bs[k][tx*4];
            float4 b1 = *(const float4*)&Bs[k][64 + tx*4];
            float aa[8] = {a0.x,a0.y,a0.z,a0.w,a1.x,a1.y,a1.z,a1.w};
            float bb[8] = {b0.x,b0.y,b0.z,b0.w,b1.x,b1.y,b1.z,b1.w};
#pragma unroll
            for (int i = 0; i < 8; i++)
#pragma unroll
                for (int j = 0; j < 8; j++) acc[i][j] += aa[i]*bb[j];
        }
        __syncthreads();
    }

    int rws[8], cls_[8];
#pragma unroll
    for (int i = 0; i < 4; i++) {
        rws[i] = ty*4 + i; rws[4+i] = 64 + ty*4 + i;
        cls_[i] = tx*4 + i; cls_[4+i] = 64 + tx*4 + i;
    }
    float bias[8];
#pragma unroll
    for (int j = 0; j < 8; j++) {
        int g = nloc0 + cls_[j];
        bias[j] = bih[g] + bhh[g];
    }
#pragma unroll
    for (int i = 0; i < 8; i++) {
        int m = m0 + rws[i];
        int bidx = m >> 8, t = m & 255;
        size_t base = ((size_t)(dir*TT + t) * BB + bidx) * GG + nloc0;
#pragma unroll
        for (int j = 0; j < 8; j++)
            g_xp[base + cls_[j]] = acc[i][j] + bias[j];
    }
}

// ---------------- kernel 3: persistent bidirectional LSTM --------------------
__device__ __forceinline__ float sigf(float x) { return 1.f / (1.f + expf(-x)); }

__global__ __launch_bounds__(256, 1) void k_lstm(
    const float* __restrict__ whhf, const float* __restrict__ whhb)
{
    extern __shared__ float sm[];
    float* Ws = sm;                    // [32][516]
    float* hs = sm + 32*516;           // [512][32]
    float* gs = hs + 512*32;           // [32][33]

    int bx = blockIdx.x;
    int d = bx >> 6;                   // direction
    int blk = bx & 63;
    int colbase = blk * 8;
    int tid = threadIdx.x;
    const float* whh = d ? whhb : whhf;

    // Persistently load this block's 32 W_hh rows into smem
    for (int q = tid; q < 32*128; q += 256) {
        int r = q >> 7, kq = q & 127;
        int grow = (r >> 3) * HH + colbase + (r & 7);
        float4 wv = *(const float4*)(whh + (size_t)grow * HH + kq*4);
        *(float4*)(Ws + r*516 + kq*4) = wv;
    }

    // Zero h0 (buffer 0) for our chunk; zero our flag
    {
        int b = tid & 31, col = tid >> 5;
        __stcg(&g_hst[((0*2 + d)*HH + colbase + col)*BB + b], 0.f);
        if (tid == 0) ((volatile int*)g_flags)[bx] = 0;
    }
    __threadfence();
    // one-shot grid barrier (monotone generation, replay-safe)
    if (tid == 0) {
        unsigned gen = ((volatile unsigned*)&g_bargen)[0];
        if (atomicAdd(&g_barcnt, 1u) == (unsigned)(gridDim.x - 1)) {
            g_barcnt = 0u;
            __threadfence();
            atomicAdd(&g_bargen, 1u);
        } else {
            while (((volatile unsigned*)&g_bargen)[0] == gen) { }
        }
    }
    __syncthreads();
    __threadfence();

    int r = tid & 31, bq = tid >> 5;   // GEMM mapping
    int typ = r >> 3, col = r & 7;
    int grow = typ * HH + colbase + col;
    int sb = tid & 31, scol = tid >> 5; // state mapping
    int kidx = colbase + scol;
    float c = 0.f;

    for (int t = 0; t < TT; t++) {
        int par_in = t % 3, par_out = (t + 1) % 3;
        int tt = d ? (TT - 1 - t) : t;

        if (t > 0) {
            if (tid < 64) {
                volatile int* vf = (volatile int*)(g_flags + d*64);
                while (vf[tid] < t) { }
            }
            __syncthreads();
            __threadfence();
        }
        // stage h_t into smem (same [k][b] layout; L1-bypass loads)
        {
            const float4* src = (const float4*)(g_hst + (size_t)((par_in*2 + d)*HH)*BB);
            float4* hd = (float4*)hs;
            for (int q = tid; q < HH*BB/4; q += 256) hd[q] = __ldcg(src + q);
        }
        __syncthreads();

        // gates(r, b0..b0+3) = xp + h @ W^T
        const float* xr = g_xp + ((size_t)(d*TT + tt) * BB) * GG + grow;
        float4 acc;
        acc.x = xr[(size_t)(bq*4 + 0) * GG];
        acc.y = xr[(size_t)(bq*4 + 1) * GG];
        acc.z = xr[(size_t)(bq*4 + 2) * GG];
        acc.w = xr[(size_t)(bq*4 + 3) * GG];
        const float4* wrow = (const float4*)(Ws + r*516);
        const float4* hq = (const float4*)hs;
#pragma unroll 16
        for (int kk = 0; kk < 128; kk++) {
            float4 w4 = wrow[kk];
            float4 h0 = hq[(4*kk + 0)*8 + bq];
            float4 h1 = hq[(4*kk + 1)*8 + bq];
            float4 h2 = hq[(4*kk + 2)*8 + bq];
            float4 h3 = hq[(4*kk + 3)*8 + bq];
            acc.x += w4.x*h0.x + w4.y*h1.x + w4.z*h2.x + w4.w*h3.x;
            acc.y += w4.x*h0.y + w4.y*h1.y + w4.z*h2.y + w4.w*h3.y;
            acc.z += w4.x*h0.z + w4.y*h1.z + w4.z*h2.z + w4.w*h3.z;
            acc.w += w4.x*h0.w + w4.y*h1.w + w4.z*h2.w + w4.w*h3.w;
        }
        gs[r*33 + bq*4 + 0] = acc.x;
        gs[r*33 + bq*4 + 1] = acc.y;
        gs[r*33 + bq*4 + 2] = acc.z;
        gs[r*33 + bq*4 + 3] = acc.w;
        __syncthreads();

        // state update: thread -> (b, col)
        {
            float iv = gs[(0*8 + scol)*33 + sb];
            float fv = gs[(1*8 + scol)*33 + sb];
            float gv = gs[(2*8 + scol)*33 + sb];
            float ov = gs[(3*8 + scol)*33 + sb];
            c = sigf(fv) * c + sigf(iv) * tanhf(gv);
            float h = sigf(ov) * tanhf(c);
            __stcg(&g_hst[((par_out*2 + d)*HH + kidx)*BB + sb], h);
            g_hcat[((size_t)(sb*TT + tt))*1024 + d*HH + kidx] = h;
        }
        __threadfence();
        __syncthreads();
        if (tid == 0) ((volatile int*)g_flags)[bx] = t + 1;
    }
}

// ---------------- kernel 4: classifier (emissions) ---------------------------
__global__ void k_cls(const float* __restrict__ cw, const float* __restrict__ cb) {
    __shared__ float hsm[1024];
    int m = blockIdx.x;
    const float4* src = (const float4*)(g_hcat + (size_t)m * 1024);
    for (int i = threadIdx.x; i < 256; i += blockDim.x) ((float4*)hsm)[i] = src[i];
    __syncthreads();
    int w = threadIdx.x >> 5, lane = threadIdx.x & 31;
    if (w < CC) {
        const float* wr = cw + w * 1024;
        float s = 0.f;
        for (int j = lane; j < 1024; j += 32) s += hsm[j] * wr[j];
#pragma unroll
        for (int off = 16; off; off >>= 1) s += __shfl_down_sync(0xffffffffu, s, off);
        if (lane == 0) g_emis[(size_t)m * CC + w] = s + cb[w];
    }
}

// ---------------- kernel 5: CRF log-likelihood (mask all-true) ---------------
__global__ void k_crf(const int* __restrict__ label, const float* __restrict__ startv,
                      const float* __restrict__ endv, const float* __restrict__ trans) {
    int b = blockIdx.x, lane = threadIdx.x;
    const int* tg = label + b * TT;
    const float* em = g_emis + (size_t)b * TT * CC;

    // numerator (labels are in [0,C) so mask is all-true)
    float p = 0.f;
    for (int t = lane; t < TT; t += 32) {
        int tag = tg[t];
        p += em[t*CC + tag];
        if (t > 0) p += trans[tg[t-1]*CC + tag];
    }
#pragma unroll
    for (int off = 16; off; off >>= 1) p += __shfl_down_sync(0xffffffffu, p, off);
    float num = __shfl_sync(0xffffffffu, p, 0) ;
    // add boundary terms on lane 0's value path (broadcast later)
    float bnd = startv[tg[0]] + endv[tg[TT-1]];
    num += bnd;

    // forward algorithm: lane j owns alpha_j (lanes >= C mirror lane 0 harmlessly)
    int j = (lane < CC) ? lane : 0;
    float trc[CC];
#pragma unroll
    for (int i = 0; i < CC; i++) trc[i] = trans[i*CC + j];
    float alpha = startv[j] + em[j];
    float em_next = em[CC + j];
    for (int t = 1; t < TT; t++) {
        float a[CC];
#pragma unroll
        for (int i = 0; i < CC; i++) a[i] = __shfl_sync(0xffffffffu, alpha, i) + trc[i];
        float em_t = em_next;
        if (t < TT-1) em_next = em[(t+1)*CC + j];
        float mx = a[0];
#pragma unroll
        for (int i = 1; i < CC; i++) mx = fmaxf(mx, a[i]);
        float s = 0.f;
#pragma unroll
        for (int i = 0; i < CC; i++) s += expf(a[i] - mx);
        alpha = mx + logf(s) + em_t;
    }
    float v = alpha + endv[j];
    float mv = v;
#pragma unroll
    for (int i = 0; i < CC; i++) mv = fmaxf(mv, __shfl_sync(0xffffffffu, v, i));
    float se = expf(v - mv);
    float tot = 0.f;
#pragma unroll
    for (int i = 0; i < CC; i++) tot += __shfl_sync(0xffffffffu, se, i);
    float den = mv + logf(tot);
    if (lane == 0) g_llh[b] = num - den;
}

// ---------------- kernel 6: final reduction ----------------------------------
__global__ void k_final(float* out) {
    if (threadIdx.x == 0) {
        float s = 0.f;
        for (int i = 0; i < BB; i++) s += g_llh[i];
        out[0] = -s / (float)BB;
    }
}

// ---------------- launch ------------------------------------------------------
extern "C" void kernel_launch(void* const* d_in, const int* in_sizes, int n_in,
                              void* d_out, int out_size) {
    const int*   input  = (const int*)d_in[0];
    const int*   label  = (const int*)d_in[1];
    const float* emb    = (const float*)d_in[2];
    const float* w_ih_f = (const float*)d_in[3];
    const float* w_hh_f = (const float*)d_in[4];
    const float* b_ih_f = (const float*)d_in[5];
    const float* b_hh_f = (const float*)d_in[6];
    const float* w_ih_b = (const float*)d_in[7];
    const float* w_hh_b = (const float*)d_in[8];
    const float* b_ih_b = (const float*)d_in[9];
    const float* b_hh_b = (const float*)d_in[10];
    const float* cls_w  = (const float*)d_in[11];
    const float* cls_b  = (const float*)d_in[12];
    const float* startv = (const float*)d_in[13];
    const float* endv   = (const float*)d_in[14];
    const float* trans  = (const float*)d_in[15];

    cudaFuncSetAttribute(k_lstm, cudaFuncAttributeMaxDynamicSharedMemorySize, LSTM_SMEM_BYTES);

    k_gather<<<MTOT, 128>>>(input, emb);
    k_xpgemm<<<dim3(32, 64), 256>>>(w_ih_f, w_ih_b, b_ih_f, b_hh_f, b_ih_b, b_hh_b);
    k_lstm<<<LSTM_BLOCKS, 256, LSTM_SMEM_BYTES>>>(w_hh_f, w_hh_b);
    k_cls<<<MTOT, 288>>>(cls_w, cls_b);
    k_crf<<<BB, 32>>>(label, startv, endv, trans);
    k_final<<<1, 32>>>((float*)d_out);
}